// round 8
// baseline (speedup 1.0000x reference)
#include <cuda_runtime.h>

#define B_ 32
#define N_ 16
#define T_ 64
#define H_ 256
#define QT 128
#define NTHREADS 256

#define XT_LD 168   // Xt[k][q + 4*(k>>2) + 4*(q>>5)]; loads & stores bank-verified CF
#define NS_LD 68    // Ns[k][t ^ (t>=32?4:0)]
#define VS_LD 68    // Vs[t][h ^ (h>=32?4:0)]
#define PT_LD 160   // Pt[t][(q + 4*(q>>5)) ^ 4*((t>>3)&7)]

#define BUF_XTNS (32 * XT_LD + 32 * NS_LD)   // 7552 floats per buffer
#define OFF_NS_IN_BUF (32 * XT_LD)           // 5376
#define BUF_VS (T_ * VS_LD)                  // 4352 floats (aliases XT/NS)
#define OFF_PT (2 * BUF_XTNS)                // 15104
#define SMEM_FLOATS (OFF_PT + T_ * PT_LD)    // 25344 floats = 99 KB

__device__ float g_vbar[B_ * T_ * H_];

typedef unsigned long long u64;

__device__ __forceinline__ u64 splat2(float a) {
    u64 r; asm("mov.b64 %0, {%1, %1};" : "=l"(r) : "f"(a)); return r;
}
__device__ __forceinline__ void fma2(u64& d, u64 a, u64 b) {
    asm("fma.rn.f32x2 %0, %1, %2, %0;" : "+l"(d) : "l"(a), "l"(b));
}
__device__ __forceinline__ void unpack2(float& lo, float& hi, u64 v) {
    asm("mov.b64 {%0, %1}, %2;" : "=f"(lo), "=f"(hi) : "l"(v));
}

__global__ void vbar_kernel(const float* __restrict__ neigh) {
    int bt = blockIdx.x;               // b*T + t
    int b  = bt >> 6, t = bt & 63;
    int h  = threadIdx.x * 4;
    const float* p = neigh + ((size_t)(b * N_) * T_ + t) * H_ + h;
    float4 s = make_float4(0.f, 0.f, 0.f, 0.f);
#pragma unroll
    for (int n = 0; n < N_; n++) {
        float4 v = *(const float4*)(p + (size_t)n * T_ * H_);
        s.x += v.x; s.y += v.y; s.z += v.z; s.w += v.w;
    }
    const float inv = 1.0f / N_;
    s.x *= inv; s.y *= inv; s.z *= inv; s.w *= inv;
    *(float4*)(g_vbar + (size_t)bt * H_ + h) = s;
}

// neighbors_number may be int64 (jax x64) or int32; values in [1,16] never 0.
__device__ __forceinline__ int get_nn(const int* __restrict__ nn32, int b) {
    bool is64 = true;
#pragma unroll
    for (int i = 1; i < 16; i += 2) is64 = is64 && (nn32[i] == 0);
    return is64 ? nn32[2 * b] : nn32[b];
}

__global__ __launch_bounds__(NTHREADS, 2)
void attn_kernel(const float* __restrict__ node,
                 const float* __restrict__ neigh,
                 const int*   __restrict__ nn32,
                 float* __restrict__ out,    // [B, N*T, H]
                 float* __restrict__ wout)   // [B, N, T] pre-zeroed
{
    extern __shared__ float sm[];
    float* Pt = sm + OFF_PT;   // [64][PT_LD]

    const int b      = blockIdx.x >> 3;
    const int q_base = (blockIdx.x & 7) * QT;
    const int tid    = threadIdx.x;

    const float* nodeb = node  + (size_t)b * T_ * H_;
    const float* Xg    = neigh + (size_t)b * N_ * T_ * H_ + (size_t)q_base * H_;

    const float scale = rsqrtf((float)get_nn(nn32, b));

    const int tt = tid & 7;        // t/h slice (8 elems = 4 pairs)
    const int tq = tid >> 3;       // q group (4 q's)
    const int t0 = tt * 8;
    const int q0 = tq * 4;

    // staging indices
    const int cb   = tid & 7;           // X/node stage: float4 col block
    const int rb   = tid >> 3;          // X stage: row base (+32s)
    const int cv   = tid & 15;          // V stage col block
    const int tvb  = tid >> 4;          // V stage row base (+16s)
    const int vcst = (4 * cv) ^ ((cv >= 8) ? 4 : 0);

    // rotated/swizzled read columns (thread-const)
    const int aoff  = q0 + 4 * (q0 >> 5);     // rotated q base (GEMM1 a4, Pt)
    const int bxor  = (t0 & 32) ? 4 : 0;
    const int bcol0 = t0 ^ bxor;
    const int bcol1 = (t0 + 4) ^ bxor;
    const int colP  = aoff ^ (4 * tt);        // softmax store column base

    // ================= GEMM1: S[128,64] = X . node^T =================
    u64 acc2[4][4];
#pragma unroll
    for (int i = 0; i < 4; i++)
#pragma unroll
        for (int j = 0; j < 4; j++) acc2[i][j] = 0ull;

    float4 xr[4], nr[2];
#pragma unroll
    for (int s = 0; s < 4; s++)
        xr[s] = *(const float4*)(Xg + (size_t)(rb + 32 * s) * H_ + 4 * cb);
#pragma unroll
    for (int s = 0; s < 2; s++)
        nr[s] = *(const float4*)(nodeb + (size_t)(rb + 32 * s) * H_ + 4 * cb);

#pragma unroll 2
    for (int c = 0; c < 8; c++) {
        float* Xb = sm + (c & 1) * BUF_XTNS;
        float* Nb = Xb + OFF_NS_IN_BUF;
#pragma unroll
        for (int s = 0; s < 4; s++) {
            // element (k = 4cb+u, q = rb+32s) -> col = q + 4*(k>>2) + 4*(q>>5)
            //                                       = (rb+32s) + 4cb + 4s
            float* dst = Xb + (4 * cb) * XT_LD + (rb + 32 * s) + 4 * cb + 4 * s;
            dst[0 * XT_LD] = xr[s].x;
            dst[1 * XT_LD] = xr[s].y;
            dst[2 * XT_LD] = xr[s].z;
            dst[3 * XT_LD] = xr[s].w;
        }
#pragma unroll
        for (int s = 0; s < 2; s++) {
            int t = rb + 32 * s;
            int colN = t ^ ((t & 32) ? 4 : 0);
            float* dst = Nb + (4 * cb) * NS_LD + colN;
            dst[0 * NS_LD] = nr[s].x;
            dst[1 * NS_LD] = nr[s].y;
            dst[2 * NS_LD] = nr[s].z;
            dst[3 * NS_LD] = nr[s].w;
        }
        __syncthreads();
        if (c < 7) {
            int k0n = (c + 1) * 32;
#pragma unroll
            for (int s = 0; s < 4; s++)
                xr[s] = *(const float4*)(Xg + (size_t)(rb + 32 * s) * H_ + k0n + 4 * cb);
#pragma unroll
            for (int s = 0; s < 2; s++)
                nr[s] = *(const float4*)(nodeb + (size_t)(rb + 32 * s) * H_ + k0n + 4 * cb);
        }
#pragma unroll 16
        for (int kk = 0; kk < 32; kk++) {
            float4 a4 = *(const float4*)(Xb + kk * XT_LD + 4 * (kk >> 2) + aoff);
            ulonglong2 b01 = *(const ulonglong2*)(Nb + kk * NS_LD + bcol0);
            ulonglong2 b23 = *(const ulonglong2*)(Nb + kk * NS_LD + bcol1);
            u64 sa;
            sa = splat2(a4.x);
            fma2(acc2[0][0], sa, b01.x); fma2(acc2[0][1], sa, b01.y);
            fma2(acc2[0][2], sa, b23.x); fma2(acc2[0][3], sa, b23.y);
            sa = splat2(a4.y);
            fma2(acc2[1][0], sa, b01.x); fma2(acc2[1][1], sa, b01.y);
            fma2(acc2[1][2], sa, b23.x); fma2(acc2[1][3], sa, b23.y);
            sa = splat2(a4.z);
            fma2(acc2[2][0], sa, b01.x); fma2(acc2[2][1], sa, b01.y);
            fma2(acc2[2][2], sa, b23.x); fma2(acc2[2][3], sa, b23.y);
            sa = splat2(a4.w);
            fma2(acc2[3][0], sa, b01.x); fma2(acc2[3][1], sa, b01.y);
            fma2(acc2[3][2], sa, b23.x); fma2(acc2[3][3], sa, b23.y);
        }
    }

    // prefetch GEMM2's first vbar chunk: LDG latency hides under softmax+W
    const float* vbarb = g_vbar + (size_t)b * T_ * H_;
    float4 vr[4];
#pragma unroll
    for (int s = 0; s < 4; s++)
        vr[s] = *(const float4*)(vbarb + (size_t)(tvb + 16 * s) * H_ + 4 * cv);

    // ================= softmax over 64 t per query (8-lane groups) =====
#pragma unroll
    for (int i = 0; i < 4; i++) {
        float v[8];
#pragma unroll
        for (int j = 0; j < 4; j++) unpack2(v[2 * j], v[2 * j + 1], acc2[i][j]);
        float m = -1e30f;
#pragma unroll
        for (int j = 0; j < 8; j++) { v[j] *= scale; m = fmaxf(m, v[j]); }
#pragma unroll
        for (int o = 1; o < 8; o <<= 1)
            m = fmaxf(m, __shfl_xor_sync(0xffffffffu, m, o));
        float s = 0.f;
#pragma unroll
        for (int j = 0; j < 8; j++) { v[j] = __expf(v[j] - m); s += v[j]; }
#pragma unroll
        for (int o = 1; o < 8; o <<= 1)
            s += __shfl_xor_sync(0xffffffffu, s, o);
        float inv = 1.0f / s;
        // Pt[t][ (q + 4*(q>>5)) ^ 4*((t>>3)&7) ]; (t0+j)>>3 == tt, low2(q0+i)=i
#pragma unroll
        for (int j = 0; j < 8; j++)
            Pt[(t0 + j) * PT_LD + colP + i] = v[j] * inv;
    }
    __syncthreads();   // Pt visible; Xt/Ns dead -> Vs may alias

    // ================= W[b,n,t] += (1/N) * sum_q P[q,t] ================
    if (tid < T_) {
        const int txor = 4 * ((tid >> 3) & 7);
        float s = 0.f;
        const float* row = Pt + tid * PT_LD;
#pragma unroll
        for (int g4 = 0; g4 < 32; g4++) {
            int qw  = 4 * g4;
            int col = (qw + 4 * (qw >> 5)) ^ txor;   // low2 bits stay 0 -> float4 ok
            float4 w4 = *(const float4*)(row + col);
            s += (w4.x + w4.y) + (w4.z + w4.w);
        }
        s *= (1.0f / N_);
        float* wb = wout + (size_t)b * N_ * T_ + tid;
#pragma unroll
        for (int n = 0; n < N_; n++) atomicAdd(wb + n * T_, s);
    }

    // ================= GEMM2: out[128,256] = P . vbar ==================
    const int hxor  = (t0 & 32) ? 4 : 0;
    const int vcol0 = t0 ^ hxor;          // h0 = t0 (tt reused as h slice)
    const int vcol1 = (t0 + 4) ^ hxor;

    for (int hc = 0; hc < 4; hc++) {
        float* Vb = sm + (hc & 1) * BUF_VS;
#pragma unroll
        for (int s = 0; s < 4; s++)
            *(float4*)(Vb + (tvb + 16 * s) * VS_LD + vcst) = vr[s];
        __syncthreads();
        if (hc < 3) {
            int h0n = (hc + 1) * 64;
#pragma unroll
            for (int s = 0; s < 4; s++)
                vr[s] = *(const float4*)(vbarb + (size_t)(tvb + 16 * s) * H_ + h0n + 4 * cv);
        }

        u64 oacc[4][4];
#pragma unroll
        for (int i = 0; i < 4; i++)
#pragma unroll
            for (int j = 0; j < 4; j++) oacc[i][j] = 0ull;

#pragma unroll 2
        for (int tb = 0; tb < 8; tb++) {
            const int colP2 = aoff ^ (4 * tb);
#pragma unroll
            for (int j = 0; j < 8; j++) {
                const int t = 8 * tb + j;
                float4 p4 = *(const float4*)(Pt + t * PT_LD + colP2);
                ulonglong2 v01 = *(const ulonglong2*)(Vb + t * VS_LD + vcol0);
                ulonglong2 v23 = *(const ulonglong2*)(Vb + t * VS_LD + vcol1);
                u64 sp;
                sp = splat2(p4.x);
                fma2(oacc[0][0], sp, v01.x); fma2(oacc[0][1], sp, v01.y);
                fma2(oacc[0][2], sp, v23.x); fma2(oacc[0][3], sp, v23.y);
                sp = splat2(p4.y);
                fma2(oacc[1][0], sp, v01.x); fma2(oacc[1][1], sp, v01.y);
                fma2(oacc[1][2], sp, v23.x); fma2(oacc[1][3], sp, v23.y);
                sp = splat2(p4.z);
                fma2(oacc[2][0], sp, v01.x); fma2(oacc[2][1], sp, v01.y);
                fma2(oacc[2][2], sp, v23.x); fma2(oacc[2][3], sp, v23.y);
                sp = splat2(p4.w);
                fma2(oacc[3][0], sp, v01.x); fma2(oacc[3][1], sp, v01.y);
                fma2(oacc[3][2], sp, v23.x); fma2(oacc[3][3], sp, v23.y);
            }
        }
#pragma unroll
        for (int i = 0; i < 4; i++) {
            float o[8];
#pragma unroll
            for (int j = 0; j < 4; j++) unpack2(o[2 * j], o[2 * j + 1], oacc[i][j]);
            float* orow = out + ((size_t)b * (N_ * T_) + q_base + q0 + i) * H_
                              + hc * 64 + t0;
            *(float4*)(orow)     = make_float4(o[0], o[1], o[2], o[3]);
            *(float4*)(orow + 4) = make_float4(o[4], o[5], o[6], o[7]);
        }
        if (hc < 3) __syncthreads();
    }
}

extern "C" void kernel_launch(void* const* d_in, const int* in_sizes, int n_in,
                              void* d_out, int out_size) {
    const float* node  = (const float*)d_in[0];   // [B, T, H]
    const float* neigh = (const float*)d_in[1];   // [B, N, T, H]
    const int*   nn32  = (const int*)d_in[2];     // [B] int64 or int32

    float* out  = (float*)d_out;                   // [B, N*T, H]
    float* wout = out + (size_t)B_ * N_ * T_ * H_; // [B, N, T]

    cudaMemsetAsync(wout, 0, (size_t)B_ * N_ * T_ * sizeof(float));

    vbar_kernel<<<B_ * T_, 64>>>(neigh);

    size_t smem = (size_t)SMEM_FLOATS * sizeof(float);
    cudaFuncSetAttribute(attn_kernel, cudaFuncAttributeMaxDynamicSharedMemorySize, (int)smem);
    attn_kernel<<<B_ * (N_ * T_ / QT), NTHREADS, smem>>>(node, neigh, nn32, out, wout);
}